// round 16
// baseline (speedup 1.0000x reference)
#include <cuda_runtime.h>
#include <cuda_bf16.h>
#include <cstdint>

#define N_NODES 50000
#define N_EDGES 800000
#define XD 128
#define HD 256
#define YD 128

// Scratch buffers (static device allocations; legal per harness rules)
__device__ __nv_bfloat16 g_xb[(size_t)N_NODES * XD];  // bf16 copy of x
__device__ __nv_bfloat16 g_tb[(size_t)N_NODES * YD];  // bf16 t = h @ W2
__device__ float g_ax [(size_t)N_NODES * XD];          // A @ xn (fp32)
__device__ float g_inv[N_NODES];                       // 1/(rowsum(x)+1e-4)

// CSR scratch (rebuilt every launch — deterministic work)
__device__ int  g_cnt   [N_NODES];
__device__ int  g_rowptr[N_NODES + 1];
__device__ int  g_cursor[N_NODES];
__device__ int2 g_edge  [N_EDGES];             // .x = col, .y = val bits

// ---------------------------------------------------------------------------
// CSR build
// ---------------------------------------------------------------------------
__global__ __launch_bounds__(256) void csr_hist_kernel(const int* __restrict__ rows) {
    int e = blockIdx.x * blockDim.x + threadIdx.x;
    if (e < N_EDGES) atomicAdd(&g_cnt[rows[e]], 1);
}

// Two-level shfl scan over 1024 chunk-sums (CHUNK=49 rows each).
__global__ __launch_bounds__(1024) void csr_scan_kernel() {
    __shared__ int warp_tot[32];
    const int t    = threadIdx.x;
    const int lane = t & 31;
    const int wid  = t >> 5;
    const int CHUNK = (N_NODES + 1023) / 1024;   // 49
    const int base = t * CHUNK;

    int local = 0;
    #pragma unroll 7
    for (int i = 0; i < CHUNK; i++) {
        int idx = base + i;
        if (idx < N_NODES) local += g_cnt[idx];
    }
    int v = local;
    #pragma unroll
    for (int o = 1; o < 32; o <<= 1) {
        int u = __shfl_up_sync(0xFFFFFFFFu, v, o);
        if (lane >= o) v += u;
    }
    if (lane == 31) warp_tot[wid] = v;
    __syncthreads();
    if (wid == 0) {
        int w = warp_tot[lane];
        #pragma unroll
        for (int o = 1; o < 32; o <<= 1) {
            int u = __shfl_up_sync(0xFFFFFFFFu, w, o);
            if (lane >= o) w += u;
        }
        warp_tot[lane] = w;
    }
    __syncthreads();
    int incl = v + (wid > 0 ? warp_tot[wid - 1] : 0);
    int pre = incl - local;
    #pragma unroll 7
    for (int i = 0; i < CHUNK; i++) {
        int idx = base + i;
        if (idx < N_NODES) {
            g_rowptr[idx] = pre;
            g_cursor[idx] = pre;
            pre += g_cnt[idx];
        }
    }
    if (t == 1023) g_rowptr[N_NODES] = incl;
}

__global__ __launch_bounds__(256) void csr_scatter_kernel(
    const float* __restrict__ vals,
    const int*   __restrict__ rows,
    const int*   __restrict__ cols)
{
    int e = blockIdx.x * blockDim.x + threadIdx.x;
    if (e >= N_EDGES) return;
    int r = rows[e];
    int c = cols[e];
    float v = vals[e];
    int pos = atomicAdd(&g_cursor[r], 1);
    g_edge[pos] = make_int2(c, __float_as_int(v));
}

// ---------------------------------------------------------------------------
// Fused row-sum + bf16 convert: g_inv[i] = 1/(sum_j x[i,j]+1e-4); g_xb = bf16(x).
// ---------------------------------------------------------------------------
__global__ __launch_bounds__(256) void rowsum_cvt_kernel(const float* __restrict__ x) {
    int row  = (blockIdx.x * blockDim.x + threadIdx.x) >> 5;
    int lane = threadIdx.x & 31;
    if (row >= N_NODES) return;
    float4 v = reinterpret_cast<const float4*>(x + (size_t)row * XD)[lane];
    float s = v.x + v.y + v.z + v.w;
    #pragma unroll
    for (int o = 16; o > 0; o >>= 1) s += __shfl_xor_sync(0xFFFFFFFFu, s, o);
    if (lane == 0) g_inv[row] = 1.0f / (s + 1e-4f);
    __nv_bfloat162 p0 = __floats2bfloat162_rn(v.x, v.y);
    __nv_bfloat162 p1 = __floats2bfloat162_rn(v.z, v.w);
    uint2 u = make_uint2(*reinterpret_cast<uint32_t*>(&p0),
                         *reinterpret_cast<uint32_t*>(&p1));
    reinterpret_cast<uint2*>(g_xb)[(size_t)row * 32 + lane] = u;
}

// ---------------------------------------------------------------------------
// CSR SpMM, bf16 source, D=128 — half-warp per row (2 edges per warp-instr).
// ---------------------------------------------------------------------------
__device__ __forceinline__ void fma_bf16x8(float* acc, uint4 m, float v) {
    float2 f0 = __bfloat1622float2(*reinterpret_cast<__nv_bfloat162*>(&m.x));
    float2 f1 = __bfloat1622float2(*reinterpret_cast<__nv_bfloat162*>(&m.y));
    float2 f2 = __bfloat1622float2(*reinterpret_cast<__nv_bfloat162*>(&m.z));
    float2 f3 = __bfloat1622float2(*reinterpret_cast<__nv_bfloat162*>(&m.w));
    acc[0] = fmaf(v, f0.x, acc[0]); acc[1] = fmaf(v, f0.y, acc[1]);
    acc[2] = fmaf(v, f1.x, acc[2]); acc[3] = fmaf(v, f1.y, acc[3]);
    acc[4] = fmaf(v, f2.x, acc[4]); acc[5] = fmaf(v, f2.y, acc[5]);
    acc[6] = fmaf(v, f3.x, acc[6]); acc[7] = fmaf(v, f3.y, acc[7]);
}

template<bool HAS_BIAS, bool SCALE_SRC>
__global__ __launch_bounds__(256) void spmm_bf16_hw_kernel(
    const __nv_bfloat16* __restrict__ src,
    const float*         __restrict__ bias,
    float*               __restrict__ dst)
{
    int gtid = blockIdx.x * blockDim.x + threadIdx.x;
    int row  = gtid >> 4;
    int lane = threadIdx.x & 15;
    if (row >= N_NODES) return;

    int s = g_rowptr[row];
    int e = g_rowptr[row + 1];

    float acc[8];
    if (HAS_BIAS) {
        float4 b0 = reinterpret_cast<const float4*>(bias)[lane * 2];
        float4 b1 = reinterpret_cast<const float4*>(bias)[lane * 2 + 1];
        acc[0] = b0.x; acc[1] = b0.y; acc[2] = b0.z; acc[3] = b0.w;
        acc[4] = b1.x; acc[5] = b1.y; acc[6] = b1.z; acc[7] = b1.w;
    } else {
        #pragma unroll
        for (int j = 0; j < 8; j++) acc[j] = 0.f;
    }

    const uint4* src4 = reinterpret_cast<const uint4*>(src);

    int i = s;
    #pragma unroll 1
    for (; i + 4 <= e; i += 4) {
        int2 e0 = __ldg(&g_edge[i]);
        int2 e1 = __ldg(&g_edge[i + 1]);
        int2 e2 = __ldg(&g_edge[i + 2]);
        int2 e3 = __ldg(&g_edge[i + 3]);
        float v0 = __int_as_float(e0.y);
        float v1 = __int_as_float(e1.y);
        float v2 = __int_as_float(e2.y);
        float v3 = __int_as_float(e3.y);
        if (SCALE_SRC) {
            v0 *= __ldg(&g_inv[e0.x]);
            v1 *= __ldg(&g_inv[e1.x]);
            v2 *= __ldg(&g_inv[e2.x]);
            v3 *= __ldg(&g_inv[e3.x]);
        }
        uint4 m0 = __ldg(&src4[(size_t)e0.x * 16 + lane]);
        uint4 m1 = __ldg(&src4[(size_t)e1.x * 16 + lane]);
        uint4 m2 = __ldg(&src4[(size_t)e2.x * 16 + lane]);
        uint4 m3 = __ldg(&src4[(size_t)e3.x * 16 + lane]);
        fma_bf16x8(acc, m0, v0);
        fma_bf16x8(acc, m1, v1);
        fma_bf16x8(acc, m2, v2);
        fma_bf16x8(acc, m3, v3);
    }
    for (; i < e; i++) {
        int2 e0 = __ldg(&g_edge[i]);
        float v0 = __int_as_float(e0.y);
        if (SCALE_SRC) v0 *= __ldg(&g_inv[e0.x]);
        uint4 m0 = __ldg(&src4[(size_t)e0.x * 16 + lane]);
        fma_bf16x8(acc, m0, v0);
    }

    float4* drow = reinterpret_cast<float4*>(dst) + (size_t)row * 32 + lane * 2;
    drow[0] = make_float4(acc[0], acc[1], acc[2], acc[3]);
    drow[1] = make_float4(acc[4], acc[5], acc[6], acc[7]);
}

// ---------------------------------------------------------------------------
// FUSED MLP: tb = bf16( relu(A@W1 + b1) @ W2 ), per 128-row slab.
// Phase 1 accumulates H in registers (16 warps, warp tile 32x64 over N=256),
// stages H in smem as tf32, Phase 2 multiplies by W2 (warp tile 32x32, N=128).
// Eliminates the 102MB g_h global round-trip.
// ---------------------------------------------------------------------------
__device__ __forceinline__ uint32_t f2tf32(float f) {
    uint32_t r;
    asm("cvt.rna.tf32.f32 %0, %1;" : "=r"(r) : "f"(f));
    return r;
}
__device__ __forceinline__ void mma_tf32(float* d, const uint32_t* a, const uint32_t* b) {
    asm volatile("mma.sync.aligned.m16n8k8.row.col.f32.tf32.tf32.f32 "
                 "{%0,%1,%2,%3}, {%4,%5,%6,%7}, {%8,%9}, {%0,%1,%2,%3};"
                 : "+f"(d[0]), "+f"(d[1]), "+f"(d[2]), "+f"(d[3])
                 : "r"(a[0]), "r"(a[1]), "r"(a[2]), "r"(a[3]),
                   "r"(b[0]), "r"(b[1]));
}

#define FLDA  36    // As stride (32+4)
#define FLDW1 260   // Ws stride for W1 tiles (256+4)
#define FLDW2 132   // Ws stride for W2 tiles (128+4)
#define FLDH  260   // Hs stride (256+4)
#define FSMEM_AS (128 * FLDA)
#define FSMEM_WS (32 * FLDW1)
#define FSMEM_HS (128 * FLDH)
#define FUSED_SMEM_BYTES (size_t)((FSMEM_AS + FSMEM_WS + FSMEM_HS) * 4)

__global__ __launch_bounds__(512) void fused_mlp_kernel(
    const float* __restrict__ A,     // g_ax [M,128]
    const float* __restrict__ W1,    // [128,256]
    const float* __restrict__ b1,    // [256]
    const float* __restrict__ W2,    // [256,128]
    __nv_bfloat16* __restrict__ out, // g_tb [M,128]
    int M)
{
    extern __shared__ uint32_t sm[];
    uint32_t* As = sm;
    uint32_t* Ws = sm + FSMEM_AS;
    uint32_t* Hs = sm + FSMEM_AS + FSMEM_WS;

    const int tid  = threadIdx.x;
    const int lane = tid & 31;
    const int wid  = tid >> 5;          // 0..15
    const int g    = lane >> 2;
    const int tg   = lane & 3;
    const int warp_m = (wid & 3) * 32;  // 4 warps along M
    const int wn     = wid >> 2;        // 0..3 along N
    const int row0 = blockIdx.x * 128;

    float acc[2][8][4];
    #pragma unroll
    for (int mt = 0; mt < 2; mt++)
        #pragma unroll
        for (int nt = 0; nt < 8; nt++)
            #pragma unroll
            for (int j = 0; j < 4; j++) acc[mt][nt][j] = 0.f;

    // ======== Phase 1: H = relu(A @ W1 + b1),  K=128, N=256 ========
    for (int k0 = 0; k0 < XD; k0 += 32) {
        // A tile: 128 x 32  (1024 float4, 2 per thread)
        #pragma unroll
        for (int i = 0; i < 2; i++) {
            int idx = tid + 512 * i;
            int r   = idx >> 3;
            int kc  = (idx & 7) * 4;
            int gr  = row0 + r; if (gr >= M) gr = M - 1;
            float4 v = *reinterpret_cast<const float4*>(A + (size_t)gr * XD + k0 + kc);
            uint4 u = make_uint4(f2tf32(v.x), f2tf32(v.y), f2tf32(v.z), f2tf32(v.w));
            *reinterpret_cast<uint4*>(&As[r * FLDA + kc]) = u;
        }
        // W1 tile: 32 x 256  (2048 float4, 4 per thread)
        #pragma unroll
        for (int i = 0; i < 4; i++) {
            int idx = tid + 512 * i;
            int kk  = idx >> 6;          // 0..31
            int c   = (idx & 63) * 4;    // 0..252
            float4 v = *reinterpret_cast<const float4*>(W1 + (size_t)(k0 + kk) * HD + c);
            uint4 u = make_uint4(f2tf32(v.x), f2tf32(v.y), f2tf32(v.z), f2tf32(v.w));
            *reinterpret_cast<uint4*>(&Ws[kk * FLDW1 + c]) = u;
        }
        __syncthreads();

        #pragma unroll
        for (int ks = 0; ks < 32; ks += 8) {
            uint32_t afr[2][4];
            #pragma unroll
            for (int mt = 0; mt < 2; mt++) {
                int r = warp_m + mt * 16 + g;
                afr[mt][0] = As[(r    ) * FLDA + ks + tg];
                afr[mt][1] = As[(r + 8) * FLDA + ks + tg];
                afr[mt][2] = As[(r    ) * FLDA + ks + tg + 4];
                afr[mt][3] = As[(r + 8) * FLDA + ks + tg + 4];
            }
            uint32_t bfr[8][2];
            #pragma unroll
            for (int nt = 0; nt < 8; nt++) {
                int c = wn * 64 + nt * 8 + g;
                bfr[nt][0] = Ws[(ks + tg    ) * FLDW1 + c];
                bfr[nt][1] = Ws[(ks + tg + 4) * FLDW1 + c];
            }
            #pragma unroll
            for (int mt = 0; mt < 2; mt++)
                #pragma unroll
                for (int nt = 0; nt < 8; nt++)
                    mma_tf32(acc[mt][nt], afr[mt], bfr[nt]);
        }
        __syncthreads();
    }

    // bias + relu + stage H into smem (tf32)
    #pragma unroll
    for (int nt = 0; nt < 8; nt++) {
        int c = wn * 64 + nt * 8 + tg * 2;
        float2 bv = *reinterpret_cast<const float2*>(b1 + c);
        #pragma unroll
        for (int mt = 0; mt < 2; mt++) {
            #pragma unroll
            for (int half = 0; half < 2; half++) {
                int m = warp_m + mt * 16 + half * 8 + g;
                float vx = fmaxf(acc[mt][nt][half * 2 + 0] + bv.x, 0.f);
                float vy = fmaxf(acc[mt][nt][half * 2 + 1] + bv.y, 0.f);
                uint2 u = make_uint2(f2tf32(vx), f2tf32(vy));
                *reinterpret_cast<uint2*>(&Hs[m * FLDH + c]) = u;
            }
        }
    }
    __syncthreads();

    // reset accumulators (phase 2 uses nt < 4)
    #pragma unroll
    for (int mt = 0; mt < 2; mt++)
        #pragma unroll
        for (int nt = 0; nt < 4; nt++)
            #pragma unroll
            for (int j = 0; j < 4; j++) acc[mt][nt][j] = 0.f;

    // ======== Phase 2: T = H @ W2,  K=256, N=128 ========
    for (int k0 = 0; k0 < HD; k0 += 32) {
        // W2 tile: 32 x 128  (1024 float4, 2 per thread)
        #pragma unroll
        for (int i = 0; i < 2; i++) {
            int idx = tid + 512 * i;
            int kk  = idx >> 5;          // 0..31
            int c   = (idx & 31) * 4;    // 0..124
            float4 v = *reinterpret_cast<const float4*>(W2 + (size_t)(k0 + kk) * YD + c);
            uint4 u = make_uint4(f2tf32(v.x), f2tf32(v.y), f2tf32(v.z), f2tf32(v.w));
            *reinterpret_cast<uint4*>(&Ws[kk * FLDW2 + c]) = u;
        }
        __syncthreads();

        #pragma unroll
        for (int ks = 0; ks < 32; ks += 8) {
            uint32_t afr[2][4];
            #pragma unroll
            for (int mt = 0; mt < 2; mt++) {
                int r = warp_m + mt * 16 + g;
                afr[mt][0] = Hs[(r    ) * FLDH + k0 + ks + tg];
                afr[mt][1] = Hs[(r + 8) * FLDH + k0 + ks + tg];
                afr[mt][2] = Hs[(r    ) * FLDH + k0 + ks + tg + 4];
                afr[mt][3] = Hs[(r + 8) * FLDH + k0 + ks + tg + 4];
            }
            uint32_t bfr[4][2];
            #pragma unroll
            for (int nt = 0; nt < 4; nt++) {
                int c = wn * 32 + nt * 8 + g;
                bfr[nt][0] = Ws[(ks + tg    ) * FLDW2 + c];
                bfr[nt][1] = Ws[(ks + tg + 4) * FLDW2 + c];
            }
            #pragma unroll
            for (int mt = 0; mt < 2; mt++)
                #pragma unroll
                for (int nt = 0; nt < 4; nt++)
                    mma_tf32(acc[mt][nt], afr[mt], bfr[nt]);
        }
        __syncthreads();
    }

    // epilogue: bf16 store (no bias here; b2 folded into spmm2)
    #pragma unroll
    for (int mt = 0; mt < 2; mt++) {
        #pragma unroll
        for (int half = 0; half < 2; half++) {
            int m = row0 + warp_m + mt * 16 + half * 8 + g;
            if (m < M) {
                #pragma unroll
                for (int nt = 0; nt < 4; nt++) {
                    int c = wn * 32 + nt * 8 + tg * 2;
                    __nv_bfloat162 p = __floats2bfloat162_rn(
                        acc[mt][nt][half * 2 + 0], acc[mt][nt][half * 2 + 1]);
                    *reinterpret_cast<__nv_bfloat162*>(out + (size_t)m * YD + c) = p;
                }
            }
        }
    }
}

// ---------------------------------------------------------------------------
extern "C" void kernel_launch(void* const* d_in, const int* in_sizes, int n_in,
                              void* d_out, int out_size) {
    const float* x        = (const float*)d_in[0];
    const float* adj_vals = (const float*)d_in[1];
    const int*   adj_row  = (const int*)  d_in[2];
    const int*   adj_col  = (const int*)  d_in[3];
    const float* W1       = (const float*)d_in[4];
    const float* b1       = (const float*)d_in[5];
    const float* W2       = (const float*)d_in[6];
    const float* b2       = (const float*)d_in[7];
    float* y = (float*)d_out;

    float* ax;
    __nv_bfloat16 *xb, *tb;
    int* cnt;
    cudaGetSymbolAddress((void**)&ax,  g_ax);
    cudaGetSymbolAddress((void**)&xb,  g_xb);
    cudaGetSymbolAddress((void**)&tb,  g_tb);
    cudaGetSymbolAddress((void**)&cnt, g_cnt);

    static bool smem_set = false;
    if (!smem_set) {
        cudaFuncSetAttribute(fused_mlp_kernel,
                             cudaFuncAttributeMaxDynamicSharedMemorySize,
                             (int)FUSED_SMEM_BYTES);
        smem_set = true;
    }

    // --- CSR build (shared by both SpMMs) ---
    cudaMemsetAsync(cnt, 0, N_NODES * sizeof(int));
    csr_hist_kernel<<<(N_EDGES + 255) / 256, 256>>>(adj_row);
    csr_scan_kernel<<<1, 1024>>>();
    csr_scatter_kernel<<<(N_EDGES + 255) / 256, 256>>>(adj_vals, adj_row, adj_col);

    // --- row sums + bf16 convert: g_inv, g_xb ---
    rowsum_cvt_kernel<<<(N_NODES * 32 + 255) / 256, 256>>>(x);

    // --- spmm1: g_ax = A @ (bf16(x) row-normalized on the fly) ---
    spmm_bf16_hw_kernel<false, true><<<(N_NODES * 16 + 255) / 256, 256>>>(xb, nullptr, ax);

    // --- fused MLP: tb = bf16( relu(g_ax@W1+b1) @ W2 ) ---
    fused_mlp_kernel<<<(N_NODES + 127) / 128, 512, FUSED_SMEM_BYTES>>>(
        ax, W1, b1, W2, tb, N_NODES);

    // --- spmm2: y = b2 + A @ tb ---
    spmm_bf16_hw_kernel<true, false><<<(N_NODES * 16 + 255) / 256, 256>>>(tb, b2, y);
}

// round 17
// speedup vs baseline: 1.0409x; 1.0409x over previous
#include <cuda_runtime.h>
#include <cuda_bf16.h>
#include <cstdint>

#define N_NODES 50000
#define N_EDGES 800000
#define XD 128
#define HD 256
#define YD 128

// Scratch buffers (static device allocations; legal per harness rules)
__device__ __nv_bfloat16 g_xb[(size_t)N_NODES * XD];  // bf16 copy of x
__device__ __nv_bfloat16 g_tb[(size_t)N_NODES * YD];  // bf16 t = h @ W2
__device__ float g_ax [(size_t)N_NODES * XD];          // A @ xn (fp32)
__device__ float g_h  [(size_t)N_NODES * HD];          // relu(ax @ W1 + b1)
__device__ float g_inv[N_NODES];                       // 1/(rowsum(x)+1e-4)

// CSR scratch (rebuilt every launch — deterministic work)
__device__ int  g_cnt   [N_NODES];
__device__ int  g_rowptr[N_NODES + 1];
__device__ int  g_cursor[N_NODES];
__device__ int2 g_edge  [N_EDGES];             // .x = col, .y = val bits

// ---------------------------------------------------------------------------
// CSR build
// ---------------------------------------------------------------------------
__global__ __launch_bounds__(256) void csr_hist_kernel(const int* __restrict__ rows) {
    int e = blockIdx.x * blockDim.x + threadIdx.x;
    if (e < N_EDGES) atomicAdd(&g_cnt[rows[e]], 1);
}

// Two-level shfl scan over 1024 chunk-sums (CHUNK=49 rows each).
__global__ __launch_bounds__(1024) void csr_scan_kernel() {
    __shared__ int warp_tot[32];
    const int t    = threadIdx.x;
    const int lane = t & 31;
    const int wid  = t >> 5;
    const int CHUNK = (N_NODES + 1023) / 1024;   // 49
    const int base = t * CHUNK;

    int local = 0;
    #pragma unroll 7
    for (int i = 0; i < CHUNK; i++) {
        int idx = base + i;
        if (idx < N_NODES) local += g_cnt[idx];
    }
    int v = local;
    #pragma unroll
    for (int o = 1; o < 32; o <<= 1) {
        int u = __shfl_up_sync(0xFFFFFFFFu, v, o);
        if (lane >= o) v += u;
    }
    if (lane == 31) warp_tot[wid] = v;
    __syncthreads();
    if (wid == 0) {
        int w = warp_tot[lane];
        #pragma unroll
        for (int o = 1; o < 32; o <<= 1) {
            int u = __shfl_up_sync(0xFFFFFFFFu, w, o);
            if (lane >= o) w += u;
        }
        warp_tot[lane] = w;
    }
    __syncthreads();
    int incl = v + (wid > 0 ? warp_tot[wid - 1] : 0);
    int pre = incl - local;
    #pragma unroll 7
    for (int i = 0; i < CHUNK; i++) {
        int idx = base + i;
        if (idx < N_NODES) {
            g_rowptr[idx] = pre;
            g_cursor[idx] = pre;
            pre += g_cnt[idx];
        }
    }
    if (t == 1023) g_rowptr[N_NODES] = incl;
}

__global__ __launch_bounds__(256) void csr_scatter_kernel(
    const float* __restrict__ vals,
    const int*   __restrict__ rows,
    const int*   __restrict__ cols)
{
    int e = blockIdx.x * blockDim.x + threadIdx.x;
    if (e >= N_EDGES) return;
    int r = rows[e];
    int c = cols[e];
    float v = vals[e];
    int pos = atomicAdd(&g_cursor[r], 1);
    g_edge[pos] = make_int2(c, __float_as_int(v));
}

// ---------------------------------------------------------------------------
// Fused row-sum + bf16 convert: g_inv[i] = 1/(sum_j x[i,j]+1e-4); g_xb = bf16(x).
// ---------------------------------------------------------------------------
__global__ __launch_bounds__(256) void rowsum_cvt_kernel(const float* __restrict__ x) {
    int row  = (blockIdx.x * blockDim.x + threadIdx.x) >> 5;
    int lane = threadIdx.x & 31;
    if (row >= N_NODES) return;
    float4 v = reinterpret_cast<const float4*>(x + (size_t)row * XD)[lane];
    float s = v.x + v.y + v.z + v.w;
    #pragma unroll
    for (int o = 16; o > 0; o >>= 1) s += __shfl_xor_sync(0xFFFFFFFFu, s, o);
    if (lane == 0) g_inv[row] = 1.0f / (s + 1e-4f);
    __nv_bfloat162 p0 = __floats2bfloat162_rn(v.x, v.y);
    __nv_bfloat162 p1 = __floats2bfloat162_rn(v.z, v.w);
    uint2 u = make_uint2(*reinterpret_cast<uint32_t*>(&p0),
                         *reinterpret_cast<uint32_t*>(&p1));
    reinterpret_cast<uint2*>(g_xb)[(size_t)row * 32 + lane] = u;
}

// ---------------------------------------------------------------------------
// CSR SpMM, bf16 source, D=128 — half-warp per row (2 edges per warp-instr).
// ---------------------------------------------------------------------------
__device__ __forceinline__ void fma_bf16x8(float* acc, uint4 m, float v) {
    float2 f0 = __bfloat1622float2(*reinterpret_cast<__nv_bfloat162*>(&m.x));
    float2 f1 = __bfloat1622float2(*reinterpret_cast<__nv_bfloat162*>(&m.y));
    float2 f2 = __bfloat1622float2(*reinterpret_cast<__nv_bfloat162*>(&m.z));
    float2 f3 = __bfloat1622float2(*reinterpret_cast<__nv_bfloat162*>(&m.w));
    acc[0] = fmaf(v, f0.x, acc[0]); acc[1] = fmaf(v, f0.y, acc[1]);
    acc[2] = fmaf(v, f1.x, acc[2]); acc[3] = fmaf(v, f1.y, acc[3]);
    acc[4] = fmaf(v, f2.x, acc[4]); acc[5] = fmaf(v, f2.y, acc[5]);
    acc[6] = fmaf(v, f3.x, acc[6]); acc[7] = fmaf(v, f3.y, acc[7]);
}

template<bool HAS_BIAS, bool SCALE_SRC>
__global__ __launch_bounds__(256) void spmm_bf16_hw_kernel(
    const __nv_bfloat16* __restrict__ src,
    const float*         __restrict__ bias,
    float*               __restrict__ dst)
{
    int gtid = blockIdx.x * blockDim.x + threadIdx.x;
    int row  = gtid >> 4;
    int lane = threadIdx.x & 15;
    if (row >= N_NODES) return;

    int s = g_rowptr[row];
    int e = g_rowptr[row + 1];

    float acc[8];
    if (HAS_BIAS) {
        float4 b0 = reinterpret_cast<const float4*>(bias)[lane * 2];
        float4 b1 = reinterpret_cast<const float4*>(bias)[lane * 2 + 1];
        acc[0] = b0.x; acc[1] = b0.y; acc[2] = b0.z; acc[3] = b0.w;
        acc[4] = b1.x; acc[5] = b1.y; acc[6] = b1.z; acc[7] = b1.w;
    } else {
        #pragma unroll
        for (int j = 0; j < 8; j++) acc[j] = 0.f;
    }

    const uint4* src4 = reinterpret_cast<const uint4*>(src);

    int i = s;
    #pragma unroll 1
    for (; i + 4 <= e; i += 4) {
        int2 e0 = __ldg(&g_edge[i]);
        int2 e1 = __ldg(&g_edge[i + 1]);
        int2 e2 = __ldg(&g_edge[i + 2]);
        int2 e3 = __ldg(&g_edge[i + 3]);
        float v0 = __int_as_float(e0.y);
        float v1 = __int_as_float(e1.y);
        float v2 = __int_as_float(e2.y);
        float v3 = __int_as_float(e3.y);
        if (SCALE_SRC) {
            v0 *= __ldg(&g_inv[e0.x]);
            v1 *= __ldg(&g_inv[e1.x]);
            v2 *= __ldg(&g_inv[e2.x]);
            v3 *= __ldg(&g_inv[e3.x]);
        }
        uint4 m0 = __ldg(&src4[(size_t)e0.x * 16 + lane]);
        uint4 m1 = __ldg(&src4[(size_t)e1.x * 16 + lane]);
        uint4 m2 = __ldg(&src4[(size_t)e2.x * 16 + lane]);
        uint4 m3 = __ldg(&src4[(size_t)e3.x * 16 + lane]);
        fma_bf16x8(acc, m0, v0);
        fma_bf16x8(acc, m1, v1);
        fma_bf16x8(acc, m2, v2);
        fma_bf16x8(acc, m3, v3);
    }
    for (; i < e; i++) {
        int2 e0 = __ldg(&g_edge[i]);
        float v0 = __int_as_float(e0.y);
        if (SCALE_SRC) v0 *= __ldg(&g_inv[e0.x]);
        uint4 m0 = __ldg(&src4[(size_t)e0.x * 16 + lane]);
        fma_bf16x8(acc, m0, v0);
    }

    float4* drow = reinterpret_cast<float4*>(dst) + (size_t)row * 32 + lane * 2;
    drow[0] = make_float4(acc[0], acc[1], acc[2], acc[3]);
    drow[1] = make_float4(acc[4], acc[5], acc[6], acc[7]);
}

// ---------------------------------------------------------------------------
// TF32 tensor-core GEMM: out[M,N] = op(A[M,K] @ W[K,N] + bias)
// Block tile 128x128, BK=32, 8 warps, warp tile 32x64. OUT_BF16 stores bf16.
// ---------------------------------------------------------------------------
__device__ __forceinline__ uint32_t f2tf32(float f) {
    uint32_t r;
    asm("cvt.rna.tf32.f32 %0, %1;" : "=r"(r) : "f"(f));
    return r;
}
__device__ __forceinline__ void mma_tf32(float* d, const uint32_t* a, const uint32_t* b) {
    asm volatile("mma.sync.aligned.m16n8k8.row.col.f32.tf32.tf32.f32 "
                 "{%0,%1,%2,%3}, {%4,%5,%6,%7}, {%8,%9}, {%0,%1,%2,%3};"
                 : "+f"(d[0]), "+f"(d[1]), "+f"(d[2]), "+f"(d[3])
                 : "r"(a[0]), "r"(a[1]), "r"(a[2]), "r"(a[3]),
                   "r"(b[0]), "r"(b[1]));
}

template<int N_DIM, int K_DIM, bool RELU, bool HAS_BIAS, bool OUT_BF16>
__global__ __launch_bounds__(256) void gemm_tf32_kernel(
    const float* __restrict__ A,
    const float* __restrict__ W,
    const float* __restrict__ bias,
    void*        __restrict__ out,
    int M)
{
    constexpr int BM = 128, BN = 128, BK = 32;
    constexpr int LDA = BK + 4;   // 36
    constexpr int LDW = BN + 4;   // 132
    __shared__ uint32_t As[BM * LDA];
    __shared__ uint32_t Ws[BK * LDW];

    const int tid  = threadIdx.x;
    const int lane = tid & 31;
    const int wid  = tid >> 5;
    const int g    = lane >> 2;
    const int tg   = lane & 3;
    const int warp_m = (wid & 3) * 32;
    const int warp_n = (wid >> 2) * 64;
    const int row0 = blockIdx.x * BM;
    const int col0 = blockIdx.y * BN;

    float acc[2][8][4];
    #pragma unroll
    for (int mt = 0; mt < 2; mt++)
        #pragma unroll
        for (int nt = 0; nt < 8; nt++)
            #pragma unroll
            for (int j = 0; j < 4; j++) acc[mt][nt][j] = 0.f;

    for (int k0 = 0; k0 < K_DIM; k0 += BK) {
        #pragma unroll
        for (int i = 0; i < 4; i++) {
            int idx = tid + 256 * i;
            int r   = idx >> 3;
            int kc  = (idx & 7) * 4;
            int gr  = row0 + r; if (gr >= M) gr = M - 1;
            float4 v = *reinterpret_cast<const float4*>(A + (size_t)gr * K_DIM + k0 + kc);
            uint4 u = make_uint4(f2tf32(v.x), f2tf32(v.y), f2tf32(v.z), f2tf32(v.w));
            *reinterpret_cast<uint4*>(&As[r * LDA + kc]) = u;
        }
        #pragma unroll
        for (int i = 0; i < 4; i++) {
            int idx = tid + 256 * i;
            int kk  = idx >> 5;
            int c   = (idx & 31) * 4;
            float4 v = *reinterpret_cast<const float4*>(W + (size_t)(k0 + kk) * N_DIM + col0 + c);
            uint4 u = make_uint4(f2tf32(v.x), f2tf32(v.y), f2tf32(v.z), f2tf32(v.w));
            *reinterpret_cast<uint4*>(&Ws[kk * LDW + c]) = u;
        }
        __syncthreads();

        #pragma unroll
        for (int ks = 0; ks < BK; ks += 8) {
            uint32_t afr[2][4];
            #pragma unroll
            for (int mt = 0; mt < 2; mt++) {
                int r = warp_m + mt * 16 + g;
                afr[mt][0] = As[(r    ) * LDA + ks + tg];
                afr[mt][1] = As[(r + 8) * LDA + ks + tg];
                afr[mt][2] = As[(r    ) * LDA + ks + tg + 4];
                afr[mt][3] = As[(r + 8) * LDA + ks + tg + 4];
            }
            uint32_t bfr[8][2];
            #pragma unroll
            for (int nt = 0; nt < 8; nt++) {
                int c = warp_n + nt * 8 + g;
                bfr[nt][0] = Ws[(ks + tg    ) * LDW + c];
                bfr[nt][1] = Ws[(ks + tg + 4) * LDW + c];
            }
            #pragma unroll
            for (int mt = 0; mt < 2; mt++)
                #pragma unroll
                for (int nt = 0; nt < 8; nt++)
                    mma_tf32(acc[mt][nt], afr[mt], bfr[nt]);
        }
        __syncthreads();
    }

    float2 bv[8];
    #pragma unroll
    for (int nt = 0; nt < 8; nt++) {
        if (HAS_BIAS) {
            int c = col0 + warp_n + nt * 8 + tg * 2;
            bv[nt] = *reinterpret_cast<const float2*>(bias + c);
        } else {
            bv[nt] = make_float2(0.f, 0.f);
        }
    }
    #pragma unroll
    for (int mt = 0; mt < 2; mt++) {
        #pragma unroll
        for (int half = 0; half < 2; half++) {
            int m = row0 + warp_m + mt * 16 + half * 8 + g;
            if (m < M) {
                #pragma unroll
                for (int nt = 0; nt < 8; nt++) {
                    int c = col0 + warp_n + nt * 8 + tg * 2;
                    float vx = acc[mt][nt][half * 2 + 0] + bv[nt].x;
                    float vy = acc[mt][nt][half * 2 + 1] + bv[nt].y;
                    if (RELU) { vx = fmaxf(vx, 0.f); vy = fmaxf(vy, 0.f); }
                    if (OUT_BF16) {
                        __nv_bfloat162 p = __floats2bfloat162_rn(vx, vy);
                        *reinterpret_cast<__nv_bfloat162*>(
                            (__nv_bfloat16*)out + (size_t)m * N_DIM + c) = p;
                    } else {
                        *reinterpret_cast<float2*>(
                            (float*)out + (size_t)m * N_DIM + c) = make_float2(vx, vy);
                    }
                }
            }
        }
    }
}

// ---------------------------------------------------------------------------
extern "C" void kernel_launch(void* const* d_in, const int* in_sizes, int n_in,
                              void* d_out, int out_size) {
    const float* x        = (const float*)d_in[0];
    const float* adj_vals = (const float*)d_in[1];
    const int*   adj_row  = (const int*)  d_in[2];
    const int*   adj_col  = (const int*)  d_in[3];
    const float* W1       = (const float*)d_in[4];
    const float* b1       = (const float*)d_in[5];
    const float* W2       = (const float*)d_in[6];
    const float* b2       = (const float*)d_in[7];
    float* y = (float*)d_out;

    float *ax, *h;
    __nv_bfloat16 *xb, *tb;
    int* cnt;
    cudaGetSymbolAddress((void**)&ax,  g_ax);
    cudaGetSymbolAddress((void**)&h,   g_h);
    cudaGetSymbolAddress((void**)&xb,  g_xb);
    cudaGetSymbolAddress((void**)&tb,  g_tb);
    cudaGetSymbolAddress((void**)&cnt, g_cnt);

    // One-time host-side resources (no device memory involved).
    static cudaStream_t s2 = nullptr;
    static cudaEvent_t ev_fork = nullptr, ev_join = nullptr;
    if (s2 == nullptr) {
        cudaStreamCreateWithFlags(&s2, cudaStreamNonBlocking);
        cudaEventCreateWithFlags(&ev_fork, cudaEventDisableTiming);
        cudaEventCreateWithFlags(&ev_join, cudaEventDisableTiming);
    }

    // --- fork: rowsum_cvt (independent of CSR build) runs on s2 ---
    cudaEventRecord(ev_fork, 0);
    cudaStreamWaitEvent(s2, ev_fork, 0);
    rowsum_cvt_kernel<<<(N_NODES * 32 + 255) / 256, 256, 0, s2>>>(x);
    cudaEventRecord(ev_join, s2);

    // --- CSR build chain on the main stream (overlaps with rowsum_cvt) ---
    cudaMemsetAsync(cnt, 0, N_NODES * sizeof(int));
    csr_hist_kernel<<<(N_EDGES + 255) / 256, 256>>>(adj_row);
    csr_scan_kernel<<<1, 1024>>>();
    csr_scatter_kernel<<<(N_EDGES + 255) / 256, 256>>>(adj_vals, adj_row, adj_col);

    // --- join: spmm1 needs both branches ---
    cudaStreamWaitEvent(0, ev_join, 0);

    // --- spmm1: g_ax = A @ (bf16(x) row-normalized on the fly) ---
    spmm_bf16_hw_kernel<false, true><<<(N_NODES * 16 + 255) / 256, 256>>>(xb, nullptr, ax);

    // --- gemm1: g_h = relu(g_ax @ W1 + b1)  [50000x256], K=128, fp32 out ---
    {
        dim3 grid((N_NODES + 127) / 128, HD / 128);
        gemm_tf32_kernel<HD, XD, true, true, false><<<grid, 256>>>(ax, W1, b1, h, N_NODES);
    }
    // --- gemm2: tb = bf16(g_h @ W2)  [50000x128], K=256 ---
    {
        dim3 grid((N_NODES + 127) / 128, YD / 128);
        gemm_tf32_kernel<YD, HD, false, false, true><<<grid, 256>>>(h, W2, nullptr, tb, N_NODES);
    }
    // --- spmm2: y = b2 + A @ tb ---
    spmm_bf16_hw_kernel<true, false><<<(N_NODES * 16 + 255) / 256, 256>>>(tb, b2, y);
}